// round 14
// baseline (speedup 1.0000x reference)
#include <cuda_runtime.h>
#include <math.h>
#include <stdint.h>

#define NN 262144
#define DD 16
#define KK 64
#define TAUF 0.1f
#define DLOG2PI 1.8378770664093454835
#define L2E 1.4426950408889634f
#define LN2 0.6931471805599453f

#define TPB 64             // threads per block (2 warps)
#define RPB 128            // rows per block (2 rows per thread)
#define ZGRID (NN / RPB)   // 2048

// ---------------- device globals ----------------
__device__ float g_sumlogpi;
__device__ unsigned g_minkey[DD] = {
    0xFFFFFFFFu,0xFFFFFFFFu,0xFFFFFFFFu,0xFFFFFFFFu,0xFFFFFFFFu,0xFFFFFFFFu,0xFFFFFFFFu,0xFFFFFFFFu,
    0xFFFFFFFFu,0xFFFFFFFFu,0xFFFFFFFFu,0xFFFFFFFFu,0xFFFFFFFFu,0xFFFFFFFFu,0xFFFFFFFFu,0xFFFFFFFFu};
__device__ unsigned g_maxkey[DD] = {0,0,0,0,0,0,0,0,0,0,0,0,0,0,0,0};
__device__ float g_partial[ZGRID];
__device__ unsigned g_ctr = 0;

// ---------------- helpers ----------------
__device__ __forceinline__ unsigned fkey(float f) {
    unsigned u = __float_as_uint(f);
    return (u & 0x80000000u) ? ~u : (u | 0x80000000u);
}
__device__ __forceinline__ float fdec(unsigned k) {
    unsigned u = (k & 0x80000000u) ? (k & 0x7FFFFFFFu) : ~k;
    return __uint_as_float(u);
}
__device__ __forceinline__ float ex2f(float x) {
    float y; asm("ex2.approx.f32 %0, %1;" : "=f"(y) : "f"(x)); return y;
}
__device__ __forceinline__ float lg2f(float x) {
    float y; asm("lg2.approx.f32 %0, %1;" : "=f"(y) : "f"(x)); return y;
}
__device__ __forceinline__ unsigned long long pk2(float lo, float hi) {
    unsigned long long r;
    asm("mov.b64 %0, {%1, %2};" : "=l"(r) : "f"(lo), "f"(hi));
    return r;
}
#define FMA2(d, a, b, c) \
    asm("fma.rn.f32x2 %0, %1, %2, %3;" : "=l"(d) : "l"(a), "l"(b), "l"(c))
#define ADD2(d, a, b) \
    asm("add.rn.f32x2 %0, %1, %2;" : "=l"(d) : "l"(a), "l"(b))
__device__ __forceinline__ void upk2(unsigned long long v, float& lo, float& hi) {
    asm("mov.b64 {%0, %1}, %2;" : "=f"(lo), "=f"(hi) : "l"(v));
}

// ---------------- single fused kernel (2 rows/thread, fine-grained blocks) ----------------
__global__ void __launch_bounds__(TPB, 10) zloss_kernel(const float* __restrict__ met,
                                                        const float* __restrict__ z,
                                                        const float* __restrict__ mu,
                                                        const float* __restrict__ pi,
                                                        const float* __restrict__ rv,
                                                        const float* __restrict__ lambda_mu,
                                                        const float* __restrict__ bv,
                                                        const float* __restrict__ Cv,
                                                        float* __restrict__ out) {
    __shared__ float4 swq[KK * 5];      // per k: w[0..15] (4xf4) + (A, C, lp2, 0)   5 KB
    __shared__ float SZ[RPB * 33];      // staged half-z (32 cols), stride-33        16.9 KB
    __shared__ float spi[KK];
    __shared__ float slse;
    __shared__ float sred[2];
    __shared__ float smn[2][DD], smx[2][DD];
    __shared__ unsigned s_last;

    const int t = threadIdx.x;
    const int lane = t & 31;
    const int wid = t >> 5;

    // ---- prep: softmax(pi) ----
    if (t < KK) spi[t] = pi[t];
    __syncthreads();
    if (t < 32) {
        float a = spi[t], b2 = spi[t + 32];
        float m = fmaxf(a, b2);
#pragma unroll
        for (int off = 16; off; off >>= 1)
            m = fmaxf(m, __shfl_xor_sync(0xffffffffu, m, off));
        float es = __expf(a - m) + __expf(b2 - m);
        float sp = a + b2;
#pragma unroll
        for (int off = 16; off; off >>= 1) {
            es += __shfl_xor_sync(0xffffffffu, es, off);
            sp += __shfl_xor_sync(0xffffffffu, sp, off);
        }
        float lse = m + __logf(es);
        if (t == 0) {
            slse = lse;
            if (blockIdx.x == 0) g_sumlogpi = sp - 64.f * lse;
        }
    }
    __syncthreads();

    // ---- prep: per-k constants into swq (t covers all 64 k) ----
    {
        float lp2 = (spi[t] - slse) * L2E;
        float rk = rv[t];
        float ie = __expf(-rk);
        float sc = L2E * ie;
        const float4* mu4 = reinterpret_cast<const float4*>(mu + t * DD);
        float msq = 0.f;
#pragma unroll
        for (int q = 0; q < 4; q++) {
            float4 mq = mu4[q];
            msq = fmaf(mq.x, mq.x, msq); msq = fmaf(mq.y, mq.y, msq);
            msq = fmaf(mq.z, mq.z, msq); msq = fmaf(mq.w, mq.w, msq);
            swq[t * 5 + q] = make_float4(sc * mq.x, sc * mq.y, sc * mq.z, sc * mq.w);
        }
        float alpha = -0.5f * ie;
        float beta  = -0.5f * 16.f * (rk + (float)DLOG2PI);
        swq[t * 5 + 4] = make_float4(L2E * alpha, L2E * fmaf(alpha, msq, beta), lp2, 0.f);
    }

    // ---- load met rows A (t) and B (t+64); pack ----
    const int rowA = blockIdx.x * RPB + t;
    const int rowB = rowA + TPB;
    const float4* xpa = reinterpret_cast<const float4*>(met + (size_t)rowA * DD);
    const float4* xpb = reinterpret_cast<const float4*>(met + (size_t)rowB * DD);
    float4 a0 = xpa[0], a1 = xpa[1], a2q = xpa[2], a3 = xpa[3];
    float4 b0 = xpb[0], b1 = xpb[1], b2q = xpb[2], b3 = xpb[3];

    float xsa = 0.f, xsb = 0.f;
    xsa = fmaf(a0.x, a0.x, xsa); xsa = fmaf(a0.y, a0.y, xsa); xsa = fmaf(a0.z, a0.z, xsa); xsa = fmaf(a0.w, a0.w, xsa);
    xsa = fmaf(a1.x, a1.x, xsa); xsa = fmaf(a1.y, a1.y, xsa); xsa = fmaf(a1.z, a1.z, xsa); xsa = fmaf(a1.w, a1.w, xsa);
    xsa = fmaf(a2q.x, a2q.x, xsa); xsa = fmaf(a2q.y, a2q.y, xsa); xsa = fmaf(a2q.z, a2q.z, xsa); xsa = fmaf(a2q.w, a2q.w, xsa);
    xsa = fmaf(a3.x, a3.x, xsa); xsa = fmaf(a3.y, a3.y, xsa); xsa = fmaf(a3.z, a3.z, xsa); xsa = fmaf(a3.w, a3.w, xsa);
    xsb = fmaf(b0.x, b0.x, xsb); xsb = fmaf(b0.y, b0.y, xsb); xsb = fmaf(b0.z, b0.z, xsb); xsb = fmaf(b0.w, b0.w, xsb);
    xsb = fmaf(b1.x, b1.x, xsb); xsb = fmaf(b1.y, b1.y, xsb); xsb = fmaf(b1.z, b1.z, xsb); xsb = fmaf(b1.w, b1.w, xsb);
    xsb = fmaf(b2q.x, b2q.x, xsb); xsb = fmaf(b2q.y, b2q.y, xsb); xsb = fmaf(b2q.z, b2q.z, xsb); xsb = fmaf(b2q.w, b2q.w, xsb);
    xsb = fmaf(b3.x, b3.x, xsb); xsb = fmaf(b3.y, b3.y, xsb); xsb = fmaf(b3.z, b3.z, xsb); xsb = fmaf(b3.w, b3.w, xsb);

    unsigned long long xa[8], xb[8];
    xa[0] = pk2(a0.x, a0.y); xa[1] = pk2(a0.z, a0.w);
    xa[2] = pk2(a1.x, a1.y); xa[3] = pk2(a1.z, a1.w);
    xa[4] = pk2(a2q.x, a2q.y); xa[5] = pk2(a2q.z, a2q.w);
    xa[6] = pk2(a3.x, a3.y); xa[7] = pk2(a3.z, a3.w);
    xb[0] = pk2(b0.x, b0.y); xb[1] = pk2(b0.z, b0.w);
    xb[2] = pk2(b1.x, b1.y); xb[3] = pk2(b1.z, b1.w);
    xb[4] = pk2(b2q.x, b2q.y); xb[5] = pk2(b2q.z, b2q.w);
    xb[6] = pk2(b3.x, b3.y); xb[7] = pk2(b3.z, b3.w);

    // ---- two-phase staged main loop ----
    const float4* zg = reinterpret_cast<const float4*>(z) + (size_t)blockIdx.x * (RPB * KK / 4);
    float mva = -3.0e38f, eva = 0.f, eza = 0.f, eua = 0.f, sza = 0.f;
    float mvb = -3.0e38f, evb = 0.f, ezb = 0.f, eub = 0.f, szb = 0.f;

#pragma unroll 1
    for (int half = 0; half < 2; half++) {
        if (half) __syncthreads();
        // stage 32 z-columns for all 128 rows, pre-scaled by log2e
#pragma unroll
        for (int j = 0; j < 16; j++) {
            int idx = j * TPB + t;
            int r = idx >> 3, c = idx & 7;
            float4 v = zg[r * 16 + half * 8 + c];
            float* sp2 = &SZ[r * 33 + c * 4];
            sp2[0] = v.x * L2E; sp2[1] = v.y * L2E; sp2[2] = v.z * L2E; sp2[3] = v.w * L2E;
        }
        __syncthreads();

        const int sa = t * 33;
        const int sb = (t + TPB) * 33;
#pragma unroll 1
        for (int cch = 0; cch < 8; cch++) {         // chunks of 4 k
            float vva[4], vvb[4];
#pragma unroll
            for (int i = 0; i < 4; i++) {
                const int kk = cch * 4 + i;
                const int k = half * 32 + kk;
                const ulonglong2* wp = reinterpret_cast<const ulonglong2*>(&swq[k * 5]);
                ulonglong2 q0 = wp[0], q1 = wp[1], q2 = wp[2], q3 = wp[3];
                float4 acp = swq[k * 5 + 4];
                float base_a = fmaf(acp.x, xsa, acp.y);
                float base_b = fmaf(acp.x, xsb, acp.y);
                float z2a = SZ[sa + kk];
                float z2b = SZ[sb + kk];

                unsigned long long A0 = pk2(base_a, z2a), A1 = 0ull;
                unsigned long long B0 = pk2(base_b, z2b), B1 = 0ull;
                FMA2(A0, xa[0], q0.x, A0); FMA2(A1, xa[1], q0.y, A1);
                FMA2(B0, xb[0], q0.x, B0); FMA2(B1, xb[1], q0.y, B1);
                FMA2(A0, xa[2], q1.x, A0); FMA2(A1, xa[3], q1.y, A1);
                FMA2(B0, xb[2], q1.x, B0); FMA2(B1, xb[3], q1.y, B1);
                FMA2(A0, xa[4], q2.x, A0); FMA2(A1, xa[5], q2.y, A1);
                FMA2(B0, xb[4], q2.x, B0); FMA2(B1, xb[5], q2.y, B1);
                FMA2(A0, xa[6], q3.x, A0); FMA2(A1, xa[7], q3.y, A1);
                FMA2(B0, xb[6], q3.x, B0); FMA2(B1, xb[7], q3.y, B1);
                ADD2(A0, A0, A1);
                ADD2(B0, B0, B1);
                float alo, ahi, blo, bhi;
                upk2(A0, alo, ahi); upk2(B0, blo, bhi);
                vva[i] = alo + ahi;                // z2 + logN (log2 units)
                vvb[i] = blo + bhi;

                eza += ex2f(z2a);           ezb += ex2f(z2b);
                eua += ex2f(fmaf(-TAUF, z2a, acp.z));
                eub += ex2f(fmaf(-TAUF, z2b, acp.z));
                sza += z2a;                 szb += z2b;
            }
            float m4a = fmaxf(fmaxf(vva[0], vva[1]), fmaxf(vva[2], vva[3]));
            float m4b = fmaxf(fmaxf(vvb[0], vvb[1]), fmaxf(vvb[2], vvb[3]));
            float mna = fmaxf(mva, m4a);
            float mnb = fmaxf(mvb, m4b);
            float s4a = ex2f(vva[0] - mna) + ex2f(vva[1] - mna)
                      + ex2f(vva[2] - mna) + ex2f(vva[3] - mna);
            float s4b = ex2f(vvb[0] - mnb) + ex2f(vvb[1] - mnb)
                      + ex2f(vvb[2] - mnb) + ex2f(vvb[3] - mnb);
            eva = fmaf(eva, ex2f(mva - mna), s4a);  mva = mna;
            evb = fmaf(evb, ex2f(mvb - mnb), s4b);  mvb = mnb;
        }
    }

    float tta = LN2 * (fmaf(63.f, lg2f(eza), fmaf(-64.f, lg2f(eua), mva + lg2f(eva)))
                       - (TAUF + 1.f) * sza);
    float ttb = LN2 * (fmaf(63.f, lg2f(ezb), fmaf(-64.f, lg2f(eub), mvb + lg2f(evb)))
                       - (TAUF + 1.f) * szb);
    float tt = tta + ttb;

    // ---- per-dim min/max over both rows: warp reduce -> block -> atomics ----
#pragma unroll
    for (int i = 0; i < 8; i++) {
        float al, ah, bl, bh;
        upk2(xa[i], al, ah); upk2(xb[i], bl, bh);
        float mn0 = fminf(al, bl), mx0 = fmaxf(al, bl);
        float mn1 = fminf(ah, bh), mx1 = fmaxf(ah, bh);
#pragma unroll
        for (int off = 16; off; off >>= 1) {
            mn0 = fminf(mn0, __shfl_xor_sync(0xffffffffu, mn0, off));
            mx0 = fmaxf(mx0, __shfl_xor_sync(0xffffffffu, mx0, off));
            mn1 = fminf(mn1, __shfl_xor_sync(0xffffffffu, mn1, off));
            mx1 = fmaxf(mx1, __shfl_xor_sync(0xffffffffu, mx1, off));
        }
        if (lane == 0) {
            smn[wid][2 * i] = mn0;     smx[wid][2 * i] = mx0;
            smn[wid][2 * i + 1] = mn1; smx[wid][2 * i + 1] = mx1;
        }
    }

    // ---- block reduce tt ----
#pragma unroll
    for (int off = 16; off; off >>= 1)
        tt += __shfl_xor_sync(0xffffffffu, tt, off);
    if (lane == 0) sred[wid] = tt;
    __syncthreads();

    if (t < DD) {
        float mn = fminf(smn[0][t], smn[1][t]);
        atomicMin(&g_minkey[t], fkey(mn));
    } else if (t < 2 * DD) {
        int d = t - DD;
        float mx = fmaxf(smx[0][d], smx[1][d]);
        atomicMax(&g_maxkey[d], fkey(mx));
    }
    __syncthreads();

    if (t == 0) {
        g_partial[blockIdx.x] = sred[0] + sred[1];
        __threadfence();
        unsigned old = atomicAdd(&g_ctr, 1u);
        s_last = (old == (unsigned)(ZGRID - 1)) ? 1u : 0u;
    }
    __syncthreads();
    if (!s_last) return;

    // ================= last block: final scalar epilogue =================
    __threadfence();
    float* shR = spi;                      // reuse
    if (t < DD) shR[t] = fdec(g_maxkey[t]) - fdec(g_minkey[t]);
    __syncthreads();

    double R2 = 0.0;
#pragma unroll
    for (int d = 0; d < DD; d++) R2 += (double)shR[d] * (double)shR[d];
    const double cc = 5.0, gg = 4.0;
    const double Gd = cc / (50.0 * gg) * sqrt(R2);
    const double lgG = (double)__logf((float)Gd);

    const double LG_HALF = 0.5723649429247001;       // lgamma(0.5)
    const double LG_C    = 3.1780538303479458;       // lgamma(5)
    const double LG_G    = 1.791759469228055;        // lgamma(4)
    const double LG_64   = 201.00931639928152;       // lgamma(64)
    const double LN_HALF = -0.6931471805599453;
    const double LN_TENTH = -2.302585092994046;

    double acc = 0.0;
    for (int i = t; i < KK * DD; i += TPB) {
        int d = i & (DD - 1);
        float lam = lambda_mu[d];
        float var = lam * lam * shR[d];
        float diff = mu[i] - bv[i];
        float bb = bv[i];
        acc += (double)(0.5f * diff * diff / var) + (double)(0.5f * bb * bb);
    }
    for (int d = t; d < DD; d += TPB) {
        float lam = lambda_mu[d];
        float var = lam * lam * shR[d];
        acc += 0.5 * (double)KK * (double)__logf(var);
        acc -= 0.5 * LN_HALF - LG_HALF - 0.5 * (double)lam - 0.5 * (double)__expf(lam);
    }
    for (int k = t; k < KK; k += TPB) {
        float rk = rv[k], Ck = Cv[k];
        acc -= cc * (double)__logf(Ck) - (cc - 1.0) * (double)rk
               - (double)Ck * (double)__expf(-rk) - LG_C;
        acc -= gg * lgG - (gg - 1.0) * (double)Ck
               - Gd * (double)__expf(-Ck) - LG_G;
    }
    const float4* p4 = reinterpret_cast<const float4*>(g_partial);
    for (int i = t; i < ZGRID / 4; i += TPB) {
        float4 v = p4[i];
        acc -= (double)v.x + (double)v.y + (double)v.z + (double)v.w;
    }

    double* dred = reinterpret_cast<double*>(SZ);    // overlay (SZ no longer needed)
    dred[t] = acc;
    __syncthreads();
#pragma unroll
    for (int s = 32; s; s >>= 1) {
        if (t < s) dred[t] += dred[t + s];
        __syncthreads();
    }
    if (t == 0) {
        double total = dred[0];
        double sumlp = (double)g_sumlogpi;
        double G0 = LG_64 + 63.0 * LN_TENTH + sumlp;          // per-row constant in con
        total -= (double)NN * G0;                             // z-loss constant part
        total += (63.0 / 64.0) * sumlp;                       // pi_loss
        total += (double)KK * 0.5 * (double)DD * DLOG2PI;     // mu_loss const
        total += 0.5 * (double)KK * (double)DD * DLOG2PI;     // b_loss const
        out[0] = (float)total;
        atomicExch(&g_ctr, 0u);                               // reset for graph replay
    }
}

// ---------------- launch ----------------
extern "C" void kernel_launch(void* const* d_in, const int* in_sizes, int n_in,
                              void* d_out, int out_size) {
    const float* met = (const float*)d_in[0];
    const float* mu  = (const float*)d_in[1];
    const float* pi  = (const float*)d_in[2];
    const float* lam = (const float*)d_in[3];
    const float* b   = (const float*)d_in[4];
    const float* C   = (const float*)d_in[5];
    const float* r   = (const float*)d_in[6];
    const float* z   = (const float*)d_in[7];
    (void)in_sizes; (void)n_in; (void)out_size;

    zloss_kernel<<<ZGRID, TPB>>>(met, z, mu, pi, r, lam, b, C, (float*)d_out);
}

// round 15
// speedup vs baseline: 1.0412x; 1.0412x over previous
#include <cuda_runtime.h>
#include <math.h>
#include <stdint.h>

#define NN 262144
#define DD 16
#define KK 64
#define TAUF 0.1f
#define DLOG2PI 1.8378770664093454835
#define L2E 1.4426950408889634f
#define LN2 0.6931471805599453f

#define TPB 128            // threads per block
#define RPB 256            // rows per block (2 rows per thread)
#define ZGRID (NN / RPB)   // 1024
#define SSTR 20            // smem row stride (16 z cols + 4 pad), float4-aligned

// ---------------- device globals ----------------
__device__ float g_sumlogpi;
__device__ unsigned g_minkey[DD] = {
    0xFFFFFFFFu,0xFFFFFFFFu,0xFFFFFFFFu,0xFFFFFFFFu,0xFFFFFFFFu,0xFFFFFFFFu,0xFFFFFFFFu,0xFFFFFFFFu,
    0xFFFFFFFFu,0xFFFFFFFFu,0xFFFFFFFFu,0xFFFFFFFFu,0xFFFFFFFFu,0xFFFFFFFFu,0xFFFFFFFFu,0xFFFFFFFFu};
__device__ unsigned g_maxkey[DD] = {0,0,0,0,0,0,0,0,0,0,0,0,0,0,0,0};
__device__ float g_partial[ZGRID];
__device__ unsigned g_ctr = 0;

// ---------------- helpers ----------------
__device__ __forceinline__ unsigned fkey(float f) {
    unsigned u = __float_as_uint(f);
    return (u & 0x80000000u) ? ~u : (u | 0x80000000u);
}
__device__ __forceinline__ float fdec(unsigned k) {
    unsigned u = (k & 0x80000000u) ? (k & 0x7FFFFFFFu) : ~k;
    return __uint_as_float(u);
}
__device__ __forceinline__ float ex2f(float x) {
    float y; asm("ex2.approx.f32 %0, %1;" : "=f"(y) : "f"(x)); return y;
}
__device__ __forceinline__ float lg2f(float x) {
    float y; asm("lg2.approx.f32 %0, %1;" : "=f"(y) : "f"(x)); return y;
}
__device__ __forceinline__ unsigned long long pk2(float lo, float hi) {
    unsigned long long r;
    asm("mov.b64 %0, {%1, %2};" : "=l"(r) : "f"(lo), "f"(hi));
    return r;
}
#define FMA2(d, a, b, c) \
    asm("fma.rn.f32x2 %0, %1, %2, %3;" : "=l"(d) : "l"(a), "l"(b), "l"(c))
#define ADD2(d, a, b) \
    asm("add.rn.f32x2 %0, %1, %2;" : "=l"(d) : "l"(a), "l"(b))
__device__ __forceinline__ void upk2(unsigned long long v, float& lo, float& hi) {
    asm("mov.b64 {%0, %1}, %2;" : "=f"(lo), "=f"(hi) : "l"(v));
}

// ---------------- single fused kernel (2 rows/thread, quarter-staged z) ----------------
__global__ void __launch_bounds__(TPB, 6) zloss_kernel(const float* __restrict__ met,
                                                       const float* __restrict__ z,
                                                       const float* __restrict__ mu,
                                                       const float* __restrict__ pi,
                                                       const float* __restrict__ rv,
                                                       const float* __restrict__ lambda_mu,
                                                       const float* __restrict__ bv,
                                                       const float* __restrict__ Cv,
                                                       float* __restrict__ out) {
    __shared__ float4 swq[KK * 5];      // per k: w[0..15] (4xf4) + (A, C, lp2, 0)   5 KB
    __shared__ float SZ[RPB * SSTR];    // staged quarter-z (16 cols), stride-20    20 KB
    __shared__ float spi[KK];
    __shared__ float slse;
    __shared__ float sred[4];
    __shared__ float smn[4][DD], smx[4][DD];
    __shared__ unsigned s_last;

    const int t = threadIdx.x;
    const int lane = t & 31;
    const int wid = t >> 5;

    // ---- prep: softmax(pi) ----
    if (t < KK) spi[t] = pi[t];
    __syncthreads();
    if (t < 32) {
        float a = spi[t], b2 = spi[t + 32];
        float m = fmaxf(a, b2);
#pragma unroll
        for (int off = 16; off; off >>= 1)
            m = fmaxf(m, __shfl_xor_sync(0xffffffffu, m, off));
        float es = __expf(a - m) + __expf(b2 - m);
        float sp = a + b2;
#pragma unroll
        for (int off = 16; off; off >>= 1) {
            es += __shfl_xor_sync(0xffffffffu, es, off);
            sp += __shfl_xor_sync(0xffffffffu, sp, off);
        }
        float lse = m + __logf(es);
        if (t == 0) {
            slse = lse;
            if (blockIdx.x == 0) g_sumlogpi = sp - 64.f * lse;
        }
    }
    __syncthreads();

    // ---- prep: per-k constants into swq ----
    if (t < KK) {
        float lp2 = (spi[t] - slse) * L2E;
        float rk = rv[t];
        float ie = __expf(-rk);
        float sc = L2E * ie;
        const float4* mu4 = reinterpret_cast<const float4*>(mu + t * DD);
        float msq = 0.f;
#pragma unroll
        for (int q = 0; q < 4; q++) {
            float4 mq = mu4[q];
            msq = fmaf(mq.x, mq.x, msq); msq = fmaf(mq.y, mq.y, msq);
            msq = fmaf(mq.z, mq.z, msq); msq = fmaf(mq.w, mq.w, msq);
            swq[t * 5 + q] = make_float4(sc * mq.x, sc * mq.y, sc * mq.z, sc * mq.w);
        }
        float alpha = -0.5f * ie;
        float beta  = -0.5f * 16.f * (rk + (float)DLOG2PI);
        swq[t * 5 + 4] = make_float4(L2E * alpha, L2E * fmaf(alpha, msq, beta), lp2, 0.f);
    }

    // ---- load met rows A (t) and B (t+128); pack ----
    const int rowA = blockIdx.x * RPB + t;
    const int rowB = rowA + TPB;
    const float4* xpa = reinterpret_cast<const float4*>(met + (size_t)rowA * DD);
    const float4* xpb = reinterpret_cast<const float4*>(met + (size_t)rowB * DD);
    float4 a0 = xpa[0], a1 = xpa[1], a2q = xpa[2], a3 = xpa[3];
    float4 b0 = xpb[0], b1 = xpb[1], b2q = xpb[2], b3 = xpb[3];

    float xsa = 0.f, xsb = 0.f;
    xsa = fmaf(a0.x, a0.x, xsa); xsa = fmaf(a0.y, a0.y, xsa); xsa = fmaf(a0.z, a0.z, xsa); xsa = fmaf(a0.w, a0.w, xsa);
    xsa = fmaf(a1.x, a1.x, xsa); xsa = fmaf(a1.y, a1.y, xsa); xsa = fmaf(a1.z, a1.z, xsa); xsa = fmaf(a1.w, a1.w, xsa);
    xsa = fmaf(a2q.x, a2q.x, xsa); xsa = fmaf(a2q.y, a2q.y, xsa); xsa = fmaf(a2q.z, a2q.z, xsa); xsa = fmaf(a2q.w, a2q.w, xsa);
    xsa = fmaf(a3.x, a3.x, xsa); xsa = fmaf(a3.y, a3.y, xsa); xsa = fmaf(a3.z, a3.z, xsa); xsa = fmaf(a3.w, a3.w, xsa);
    xsb = fmaf(b0.x, b0.x, xsb); xsb = fmaf(b0.y, b0.y, xsb); xsb = fmaf(b0.z, b0.z, xsb); xsb = fmaf(b0.w, b0.w, xsb);
    xsb = fmaf(b1.x, b1.x, xsb); xsb = fmaf(b1.y, b1.y, xsb); xsb = fmaf(b1.z, b1.z, xsb); xsb = fmaf(b1.w, b1.w, xsb);
    xsb = fmaf(b2q.x, b2q.x, xsb); xsb = fmaf(b2q.y, b2q.y, xsb); xsb = fmaf(b2q.z, b2q.z, xsb); xsb = fmaf(b2q.w, b2q.w, xsb);
    xsb = fmaf(b3.x, b3.x, xsb); xsb = fmaf(b3.y, b3.y, xsb); xsb = fmaf(b3.z, b3.z, xsb); xsb = fmaf(b3.w, b3.w, xsb);

    unsigned long long xa[8], xb[8];
    xa[0] = pk2(a0.x, a0.y); xa[1] = pk2(a0.z, a0.w);
    xa[2] = pk2(a1.x, a1.y); xa[3] = pk2(a1.z, a1.w);
    xa[4] = pk2(a2q.x, a2q.y); xa[5] = pk2(a2q.z, a2q.w);
    xa[6] = pk2(a3.x, a3.y); xa[7] = pk2(a3.z, a3.w);
    xb[0] = pk2(b0.x, b0.y); xb[1] = pk2(b0.z, b0.w);
    xb[2] = pk2(b1.x, b1.y); xb[3] = pk2(b1.z, b1.w);
    xb[4] = pk2(b2q.x, b2q.y); xb[5] = pk2(b2q.z, b2q.w);
    xb[6] = pk2(b3.x, b3.y); xb[7] = pk2(b3.z, b3.w);

    // ---- quarter-staged main loop ----
    const float4* zg = reinterpret_cast<const float4*>(z) + (size_t)blockIdx.x * (RPB * KK / 4);
    float mva = -3.0e38f, eva = 0.f, eza = 0.f, eua = 0.f, sza = 0.f;
    float mvb = -3.0e38f, evb = 0.f, ezb = 0.f, eub = 0.f, szb = 0.f;

    const int sa = t * SSTR;
    const int sb = (t + TPB) * SSTR;

#pragma unroll 1
    for (int qt = 0; qt < 4; qt++) {
        if (qt) __syncthreads();                 // readers of previous quarter done
        // stage 16 z-columns for all 256 rows, pre-scaled by log2e
#pragma unroll
        for (int j = 0; j < 8; j++) {
            int idx = j * TPB + t;
            int r = idx >> 2, c = idx & 3;
            float4 v = zg[r * 16 + qt * 4 + c];
            float* sp2 = &SZ[r * SSTR + c * 4];
            sp2[0] = v.x * L2E; sp2[1] = v.y * L2E; sp2[2] = v.z * L2E; sp2[3] = v.w * L2E;
        }
        __syncthreads();

#pragma unroll 1
        for (int cch = 0; cch < 4; cch++) {      // chunks of 4 k
            float vva[4], vvb[4];
            const float4 za4 = *reinterpret_cast<const float4*>(&SZ[sa + cch * 4]);
            const float4 zb4 = *reinterpret_cast<const float4*>(&SZ[sb + cch * 4]);
            const float z4a[4] = { za4.x, za4.y, za4.z, za4.w };
            const float z4b[4] = { zb4.x, zb4.y, zb4.z, zb4.w };
#pragma unroll
            for (int i = 0; i < 4; i++) {
                const int k = qt * 16 + cch * 4 + i;
                const ulonglong2* wp = reinterpret_cast<const ulonglong2*>(&swq[k * 5]);
                ulonglong2 q0 = wp[0], q1 = wp[1], q2 = wp[2], q3 = wp[3];
                float4 acp = swq[k * 5 + 4];
                float base_a = fmaf(acp.x, xsa, acp.y);
                float base_b = fmaf(acp.x, xsb, acp.y);
                float z2a = z4a[i];
                float z2b = z4b[i];

                unsigned long long A0 = pk2(base_a, z2a), A1 = 0ull;
                unsigned long long B0 = pk2(base_b, z2b), B1 = 0ull;
                FMA2(A0, xa[0], q0.x, A0); FMA2(A1, xa[1], q0.y, A1);
                FMA2(B0, xb[0], q0.x, B0); FMA2(B1, xb[1], q0.y, B1);
                FMA2(A0, xa[2], q1.x, A0); FMA2(A1, xa[3], q1.y, A1);
                FMA2(B0, xb[2], q1.x, B0); FMA2(B1, xb[3], q1.y, B1);
                FMA2(A0, xa[4], q2.x, A0); FMA2(A1, xa[5], q2.y, A1);
                FMA2(B0, xb[4], q2.x, B0); FMA2(B1, xb[5], q2.y, B1);
                FMA2(A0, xa[6], q3.x, A0); FMA2(A1, xa[7], q3.y, A1);
                FMA2(B0, xb[6], q3.x, B0); FMA2(B1, xb[7], q3.y, B1);
                ADD2(A0, A0, A1);
                ADD2(B0, B0, B1);
                float alo, ahi, blo, bhi;
                upk2(A0, alo, ahi); upk2(B0, blo, bhi);
                vva[i] = alo + ahi;                // z2 + logN (log2 units)
                vvb[i] = blo + bhi;

                eza += ex2f(z2a);           ezb += ex2f(z2b);
                eua += ex2f(fmaf(-TAUF, z2a, acp.z));
                eub += ex2f(fmaf(-TAUF, z2b, acp.z));
                sza += z2a;                 szb += z2b;
            }
            float m4a = fmaxf(fmaxf(vva[0], vva[1]), fmaxf(vva[2], vva[3]));
            float m4b = fmaxf(fmaxf(vvb[0], vvb[1]), fmaxf(vvb[2], vvb[3]));
            float mna = fmaxf(mva, m4a);
            float mnb = fmaxf(mvb, m4b);
            float s4a = ex2f(vva[0] - mna) + ex2f(vva[1] - mna)
                      + ex2f(vva[2] - mna) + ex2f(vva[3] - mna);
            float s4b = ex2f(vvb[0] - mnb) + ex2f(vvb[1] - mnb)
                      + ex2f(vvb[2] - mnb) + ex2f(vvb[3] - mnb);
            eva = fmaf(eva, ex2f(mva - mna), s4a);  mva = mna;
            evb = fmaf(evb, ex2f(mvb - mnb), s4b);  mvb = mnb;
        }
    }

    float tta = LN2 * (fmaf(63.f, lg2f(eza), fmaf(-64.f, lg2f(eua), mva + lg2f(eva)))
                       - (TAUF + 1.f) * sza);
    float ttb = LN2 * (fmaf(63.f, lg2f(ezb), fmaf(-64.f, lg2f(eub), mvb + lg2f(evb)))
                       - (TAUF + 1.f) * szb);
    float tt = tta + ttb;

    // ---- per-dim min/max over both rows: warp reduce -> block -> atomics ----
#pragma unroll
    for (int i = 0; i < 8; i++) {
        float al, ah, bl, bh;
        upk2(xa[i], al, ah); upk2(xb[i], bl, bh);
        float mn0 = fminf(al, bl), mx0 = fmaxf(al, bl);
        float mn1 = fminf(ah, bh), mx1 = fmaxf(ah, bh);
#pragma unroll
        for (int off = 16; off; off >>= 1) {
            mn0 = fminf(mn0, __shfl_xor_sync(0xffffffffu, mn0, off));
            mx0 = fmaxf(mx0, __shfl_xor_sync(0xffffffffu, mx0, off));
            mn1 = fminf(mn1, __shfl_xor_sync(0xffffffffu, mn1, off));
            mx1 = fmaxf(mx1, __shfl_xor_sync(0xffffffffu, mx1, off));
        }
        if (lane == 0) {
            smn[wid][2 * i] = mn0;     smx[wid][2 * i] = mx0;
            smn[wid][2 * i + 1] = mn1; smx[wid][2 * i + 1] = mx1;
        }
    }

    // ---- block reduce tt ----
#pragma unroll
    for (int off = 16; off; off >>= 1)
        tt += __shfl_xor_sync(0xffffffffu, tt, off);
    if (lane == 0) sred[wid] = tt;
    __syncthreads();

    if (t < DD) {
        float mn = fminf(fminf(smn[0][t], smn[1][t]), fminf(smn[2][t], smn[3][t]));
        atomicMin(&g_minkey[t], fkey(mn));
    } else if (t < 2 * DD) {
        int d = t - DD;
        float mx = fmaxf(fmaxf(smx[0][d], smx[1][d]), fmaxf(smx[2][d], smx[3][d]));
        atomicMax(&g_maxkey[d], fkey(mx));
    }
    __syncthreads();

    if (t == 0) {
        g_partial[blockIdx.x] = sred[0] + sred[1] + sred[2] + sred[3];
        __threadfence();
        unsigned old = atomicAdd(&g_ctr, 1u);
        s_last = (old == (unsigned)(ZGRID - 1)) ? 1u : 0u;
    }
    __syncthreads();
    if (!s_last) return;

    // ================= last block: final scalar epilogue =================
    __threadfence();
    float* shR = spi;                      // reuse
    if (t < DD) shR[t] = fdec(g_maxkey[t]) - fdec(g_minkey[t]);
    __syncthreads();

    double R2 = 0.0;
#pragma unroll
    for (int d = 0; d < DD; d++) R2 += (double)shR[d] * (double)shR[d];
    const double cc = 5.0, gg = 4.0;
    const double Gd = cc / (50.0 * gg) * sqrt(R2);
    const double lgG = (double)__logf((float)Gd);

    const double LG_HALF = 0.5723649429247001;       // lgamma(0.5)
    const double LG_C    = 3.1780538303479458;       // lgamma(5)
    const double LG_G    = 1.791759469228055;        // lgamma(4)
    const double LG_64   = 201.00931639928152;       // lgamma(64)
    const double LN_HALF = -0.6931471805599453;
    const double LN_TENTH = -2.302585092994046;

    double acc = 0.0;
    for (int i = t; i < KK * DD; i += TPB) {
        int d = i & (DD - 1);
        float lam = lambda_mu[d];
        float var = lam * lam * shR[d];
        float diff = mu[i] - bv[i];
        float bb = bv[i];
        acc += (double)(0.5f * diff * diff / var) + (double)(0.5f * bb * bb);
    }
    for (int d = t; d < DD; d += TPB) {
        float lam = lambda_mu[d];
        float var = lam * lam * shR[d];
        acc += 0.5 * (double)KK * (double)__logf(var);
        acc -= 0.5 * LN_HALF - LG_HALF - 0.5 * (double)lam - 0.5 * (double)__expf(lam);
    }
    for (int k = t; k < KK; k += TPB) {
        float rk = rv[k], Ck = Cv[k];
        acc -= cc * (double)__logf(Ck) - (cc - 1.0) * (double)rk
               - (double)Ck * (double)__expf(-rk) - LG_C;
        acc -= gg * lgG - (gg - 1.0) * (double)Ck
               - Gd * (double)__expf(-Ck) - LG_G;
    }
    const float4* p4 = reinterpret_cast<const float4*>(g_partial);
    for (int i = t; i < ZGRID / 4; i += TPB) {
        float4 v = p4[i];
        acc -= (double)v.x + (double)v.y + (double)v.z + (double)v.w;
    }

    double* dred = reinterpret_cast<double*>(SZ);    // overlay (SZ no longer needed)
    dred[t] = acc;
    __syncthreads();
#pragma unroll
    for (int s = 64; s; s >>= 1) {
        if (t < s) dred[t] += dred[t + s];
        __syncthreads();
    }
    if (t == 0) {
        double total = dred[0];
        double sumlp = (double)g_sumlogpi;
        double G0 = LG_64 + 63.0 * LN_TENTH + sumlp;          // per-row constant in con
        total -= (double)NN * G0;                             // z-loss constant part
        total += (63.0 / 64.0) * sumlp;                       // pi_loss
        total += (double)KK * 0.5 * (double)DD * DLOG2PI;     // mu_loss const
        total += 0.5 * (double)KK * (double)DD * DLOG2PI;     // b_loss const
        out[0] = (float)total;
        atomicExch(&g_ctr, 0u);                               // reset for graph replay
    }
}

// ---------------- launch ----------------
extern "C" void kernel_launch(void* const* d_in, const int* in_sizes, int n_in,
                              void* d_out, int out_size) {
    const float* met = (const float*)d_in[0];
    const float* mu  = (const float*)d_in[1];
    const float* pi  = (const float*)d_in[2];
    const float* lam = (const float*)d_in[3];
    const float* b   = (const float*)d_in[4];
    const float* C   = (const float*)d_in[5];
    const float* r   = (const float*)d_in[6];
    const float* z   = (const float*)d_in[7];
    (void)in_sizes; (void)n_in; (void)out_size;

    zloss_kernel<<<ZGRID, TPB>>>(met, z, mu, pi, r, lam, b, C, (float*)d_out);
}

// round 16
// speedup vs baseline: 1.1301x; 1.0853x over previous
#include <cuda_runtime.h>
#include <math.h>
#include <stdint.h>

#define NN 262144
#define DD 16
#define KK 64
#define TAUF 0.1f
#define DLOG2PI 1.8378770664093454835
#define L2E 1.4426950408889634f
#define LN2 0.6931471805599453f

#define TPB 128            // threads per block
#define RPB 256            // rows per block (2 rows per thread)
#define ZGRID (NN / RPB)   // 1024
#define SSTR 36            // smem row stride: 32 z cols + 4 pad, 16B-aligned

// ---------------- device globals ----------------
__device__ float g_sumlogpi;
__device__ unsigned g_minkey[DD] = {
    0xFFFFFFFFu,0xFFFFFFFFu,0xFFFFFFFFu,0xFFFFFFFFu,0xFFFFFFFFu,0xFFFFFFFFu,0xFFFFFFFFu,0xFFFFFFFFu,
    0xFFFFFFFFu,0xFFFFFFFFu,0xFFFFFFFFu,0xFFFFFFFFu,0xFFFFFFFFu,0xFFFFFFFFu,0xFFFFFFFFu,0xFFFFFFFFu};
__device__ unsigned g_maxkey[DD] = {0,0,0,0,0,0,0,0,0,0,0,0,0,0,0,0};
__device__ float g_partial[ZGRID];
__device__ unsigned g_ctr = 0;

// ---------------- helpers ----------------
__device__ __forceinline__ unsigned fkey(float f) {
    unsigned u = __float_as_uint(f);
    return (u & 0x80000000u) ? ~u : (u | 0x80000000u);
}
__device__ __forceinline__ float fdec(unsigned k) {
    unsigned u = (k & 0x80000000u) ? (k & 0x7FFFFFFFu) : ~k;
    return __uint_as_float(u);
}
__device__ __forceinline__ float ex2f(float x) {
    float y; asm("ex2.approx.f32 %0, %1;" : "=f"(y) : "f"(x)); return y;
}
__device__ __forceinline__ float lg2f(float x) {
    float y; asm("lg2.approx.f32 %0, %1;" : "=f"(y) : "f"(x)); return y;
}

// ---------------- single fused kernel (2 rows/thread, scalar FFMA hot loop) ----------------
__global__ void __launch_bounds__(TPB, 5) zloss_kernel(const float* __restrict__ met,
                                                       const float* __restrict__ z,
                                                       const float* __restrict__ mu,
                                                       const float* __restrict__ pi,
                                                       const float* __restrict__ rv,
                                                       const float* __restrict__ lambda_mu,
                                                       const float* __restrict__ bv,
                                                       const float* __restrict__ Cv,
                                                       float* __restrict__ out) {
    __shared__ float4 swq[KK * 5];      // per k: w[0..15] (4xf4) + (A, C, lp2, 0)   5 KB
    __shared__ float SZ[RPB * SSTR];    // staged half-z (32 cols), stride-36        36 KB
    __shared__ float spi[KK];
    __shared__ float slse;
    __shared__ float sred[4];
    __shared__ float smn[4][DD], smx[4][DD];
    __shared__ unsigned s_last;

    const int t = threadIdx.x;
    const int lane = t & 31;
    const int wid = t >> 5;

    // ---- prep: softmax(pi) ----
    if (t < KK) spi[t] = pi[t];
    __syncthreads();
    if (t < 32) {
        float a = spi[t], b2 = spi[t + 32];
        float m = fmaxf(a, b2);
#pragma unroll
        for (int off = 16; off; off >>= 1)
            m = fmaxf(m, __shfl_xor_sync(0xffffffffu, m, off));
        float es = __expf(a - m) + __expf(b2 - m);
        float sp = a + b2;
#pragma unroll
        for (int off = 16; off; off >>= 1) {
            es += __shfl_xor_sync(0xffffffffu, es, off);
            sp += __shfl_xor_sync(0xffffffffu, sp, off);
        }
        float lse = m + __logf(es);
        if (t == 0) {
            slse = lse;
            if (blockIdx.x == 0) g_sumlogpi = sp - 64.f * lse;
        }
    }
    __syncthreads();

    // ---- prep: per-k constants into swq ----
    if (t < KK) {
        float lp2 = (spi[t] - slse) * L2E;
        float rk = rv[t];
        float ie = __expf(-rk);
        float sc = L2E * ie;
        const float4* mu4 = reinterpret_cast<const float4*>(mu + t * DD);
        float msq = 0.f;
#pragma unroll
        for (int q = 0; q < 4; q++) {
            float4 mq = mu4[q];
            msq = fmaf(mq.x, mq.x, msq); msq = fmaf(mq.y, mq.y, msq);
            msq = fmaf(mq.z, mq.z, msq); msq = fmaf(mq.w, mq.w, msq);
            swq[t * 5 + q] = make_float4(sc * mq.x, sc * mq.y, sc * mq.z, sc * mq.w);
        }
        float alpha = -0.5f * ie;
        float beta  = -0.5f * 16.f * (rk + (float)DLOG2PI);
        swq[t * 5 + 4] = make_float4(L2E * alpha, L2E * fmaf(alpha, msq, beta), lp2, 0.f);
    }

    // ---- load met rows A (t) and B (t+128) as scalars ----
    const int rowA = blockIdx.x * RPB + t;
    const int rowB = rowA + TPB;
    const float4* xpa = reinterpret_cast<const float4*>(met + (size_t)rowA * DD);
    const float4* xpb = reinterpret_cast<const float4*>(met + (size_t)rowB * DD);
    float4 a0 = xpa[0], a1 = xpa[1], a2q = xpa[2], a3 = xpa[3];
    float4 b0 = xpb[0], b1 = xpb[1], b2q = xpb[2], b3 = xpb[3];
    float xA[DD] = { a0.x, a0.y, a0.z, a0.w, a1.x, a1.y, a1.z, a1.w,
                     a2q.x, a2q.y, a2q.z, a2q.w, a3.x, a3.y, a3.z, a3.w };
    float xB[DD] = { b0.x, b0.y, b0.z, b0.w, b1.x, b1.y, b1.z, b1.w,
                     b2q.x, b2q.y, b2q.z, b2q.w, b3.x, b3.y, b3.z, b3.w };

    float xsa = 0.f, xsb = 0.f;
#pragma unroll
    for (int d = 0; d < DD; d++) {
        xsa = fmaf(xA[d], xA[d], xsa);
        xsb = fmaf(xB[d], xB[d], xsb);
    }

    // ---- two-phase staged main loop ----
    const float4* zg = reinterpret_cast<const float4*>(z) + (size_t)blockIdx.x * (RPB * KK / 4);
    float mva = -3.0e38f, eva = 0.f, eza = 0.f, eua = 0.f, sza = 0.f;
    float mvb = -3.0e38f, evb = 0.f, ezb = 0.f, eub = 0.f, szb = 0.f;

    const int sa = t * SSTR;
    const int sb = (t + TPB) * SSTR;

#pragma unroll 1
    for (int half = 0; half < 2; half++) {
        if (half) __syncthreads();
        // stage 32 z-columns for all 256 rows, pre-scaled by log2e
#pragma unroll
        for (int j = 0; j < 16; j++) {
            int idx = j * TPB + t;
            int r = idx >> 3, c = idx & 7;
            float4 v = zg[r * 16 + half * 8 + c];
            *reinterpret_cast<float4*>(&SZ[r * SSTR + c * 4]) =
                make_float4(v.x * L2E, v.y * L2E, v.z * L2E, v.w * L2E);
        }
        __syncthreads();

#pragma unroll 1
        for (int cch = 0; cch < 8; cch++) {      // chunks of 4 k
            const float4 za4 = *reinterpret_cast<const float4*>(&SZ[sa + cch * 4]);
            const float4 zb4 = *reinterpret_cast<const float4*>(&SZ[sb + cch * 4]);
            const float z4a[4] = { za4.x, za4.y, za4.z, za4.w };
            const float z4b[4] = { zb4.x, zb4.y, zb4.z, zb4.w };
            sza += (za4.x + za4.y) + (za4.z + za4.w);
            szb += (zb4.x + zb4.y) + (zb4.z + zb4.w);

            float vva[4], vvb[4];
#pragma unroll
            for (int i = 0; i < 4; i++) {
                const int k = half * 32 + cch * 4 + i;
                const float4 wa = swq[k * 5 + 0];
                const float4 wb = swq[k * 5 + 1];
                const float4 wc = swq[k * 5 + 2];
                const float4 wd = swq[k * 5 + 3];
                const float4 acp = swq[k * 5 + 4];
                const float z2a = z4a[i];
                const float z2b = z4b[i];

                float pA = fmaf(acp.x, xsa, acp.y), qA = z2a;
                float pB = fmaf(acp.x, xsb, acp.y), qB = z2b;
                pA = fmaf(xA[0],  wa.x, pA); qA = fmaf(xA[1],  wa.y, qA);
                pB = fmaf(xB[0],  wa.x, pB); qB = fmaf(xB[1],  wa.y, qB);
                pA = fmaf(xA[2],  wa.z, pA); qA = fmaf(xA[3],  wa.w, qA);
                pB = fmaf(xB[2],  wa.z, pB); qB = fmaf(xB[3],  wa.w, qB);
                pA = fmaf(xA[4],  wb.x, pA); qA = fmaf(xA[5],  wb.y, qA);
                pB = fmaf(xB[4],  wb.x, pB); qB = fmaf(xB[5],  wb.y, qB);
                pA = fmaf(xA[6],  wb.z, pA); qA = fmaf(xA[7],  wb.w, qA);
                pB = fmaf(xB[6],  wb.z, pB); qB = fmaf(xB[7],  wb.w, qB);
                pA = fmaf(xA[8],  wc.x, pA); qA = fmaf(xA[9],  wc.y, qA);
                pB = fmaf(xB[8],  wc.x, pB); qB = fmaf(xB[9],  wc.y, qB);
                pA = fmaf(xA[10], wc.z, pA); qA = fmaf(xA[11], wc.w, qA);
                pB = fmaf(xB[10], wc.z, pB); qB = fmaf(xB[11], wc.w, qB);
                pA = fmaf(xA[12], wd.x, pA); qA = fmaf(xA[13], wd.y, qA);
                pB = fmaf(xB[12], wd.x, pB); qB = fmaf(xB[13], wd.y, qB);
                pA = fmaf(xA[14], wd.z, pA); qA = fmaf(xA[15], wd.w, qA);
                pB = fmaf(xB[14], wd.z, pB); qB = fmaf(xB[15], wd.w, qB);
                vva[i] = pA + qA;                  // z2 + logN (log2 units)
                vvb[i] = pB + qB;

                eza += ex2f(z2a);           ezb += ex2f(z2b);
                eua += ex2f(fmaf(-TAUF, z2a, acp.z));
                eub += ex2f(fmaf(-TAUF, z2b, acp.z));
            }
            float m4a = fmaxf(fmaxf(vva[0], vva[1]), fmaxf(vva[2], vva[3]));
            float m4b = fmaxf(fmaxf(vvb[0], vvb[1]), fmaxf(vvb[2], vvb[3]));
            float mna = fmaxf(mva, m4a);
            float mnb = fmaxf(mvb, m4b);
            float s4a = (ex2f(vva[0] - mna) + ex2f(vva[1] - mna))
                      + (ex2f(vva[2] - mna) + ex2f(vva[3] - mna));
            float s4b = (ex2f(vvb[0] - mnb) + ex2f(vvb[1] - mnb))
                      + (ex2f(vvb[2] - mnb) + ex2f(vvb[3] - mnb));
            eva = fmaf(eva, ex2f(mva - mna), s4a);  mva = mna;
            evb = fmaf(evb, ex2f(mvb - mnb), s4b);  mvb = mnb;
        }
    }

    float tta = LN2 * (fmaf(63.f, lg2f(eza), fmaf(-64.f, lg2f(eua), mva + lg2f(eva)))
                       - (TAUF + 1.f) * sza);
    float ttb = LN2 * (fmaf(63.f, lg2f(ezb), fmaf(-64.f, lg2f(eub), mvb + lg2f(evb)))
                       - (TAUF + 1.f) * szb);
    float tt = tta + ttb;

    // ---- per-dim min/max over both rows: warp reduce -> block -> atomics ----
#pragma unroll
    for (int d = 0; d < DD; d += 2) {
        float mn0 = fminf(xA[d], xB[d]),     mx0 = fmaxf(xA[d], xB[d]);
        float mn1 = fminf(xA[d + 1], xB[d + 1]), mx1 = fmaxf(xA[d + 1], xB[d + 1]);
#pragma unroll
        for (int off = 16; off; off >>= 1) {
            mn0 = fminf(mn0, __shfl_xor_sync(0xffffffffu, mn0, off));
            mx0 = fmaxf(mx0, __shfl_xor_sync(0xffffffffu, mx0, off));
            mn1 = fminf(mn1, __shfl_xor_sync(0xffffffffu, mn1, off));
            mx1 = fmaxf(mx1, __shfl_xor_sync(0xffffffffu, mx1, off));
        }
        if (lane == 0) {
            smn[wid][d] = mn0;     smx[wid][d] = mx0;
            smn[wid][d + 1] = mn1; smx[wid][d + 1] = mx1;
        }
    }

    // ---- block reduce tt ----
#pragma unroll
    for (int off = 16; off; off >>= 1)
        tt += __shfl_xor_sync(0xffffffffu, tt, off);
    if (lane == 0) sred[wid] = tt;
    __syncthreads();

    if (t < DD) {
        float mn = fminf(fminf(smn[0][t], smn[1][t]), fminf(smn[2][t], smn[3][t]));
        atomicMin(&g_minkey[t], fkey(mn));
    } else if (t < 2 * DD) {
        int d = t - DD;
        float mx = fmaxf(fmaxf(smx[0][d], smx[1][d]), fmaxf(smx[2][d], smx[3][d]));
        atomicMax(&g_maxkey[d], fkey(mx));
    }
    __syncthreads();

    if (t == 0) {
        g_partial[blockIdx.x] = sred[0] + sred[1] + sred[2] + sred[3];
        __threadfence();
        unsigned old = atomicAdd(&g_ctr, 1u);
        s_last = (old == (unsigned)(ZGRID - 1)) ? 1u : 0u;
    }
    __syncthreads();
    if (!s_last) return;

    // ================= last block: final scalar epilogue =================
    __threadfence();
    float* shR = spi;                      // reuse
    if (t < DD) shR[t] = fdec(g_maxkey[t]) - fdec(g_minkey[t]);
    __syncthreads();

    double R2 = 0.0;
#pragma unroll
    for (int d = 0; d < DD; d++) R2 += (double)shR[d] * (double)shR[d];
    const double cc = 5.0, gg = 4.0;
    const double Gd = cc / (50.0 * gg) * sqrt(R2);
    const double lgG = (double)__logf((float)Gd);

    const double LG_HALF = 0.5723649429247001;       // lgamma(0.5)
    const double LG_C    = 3.1780538303479458;       // lgamma(5)
    const double LG_G    = 1.791759469228055;        // lgamma(4)
    const double LG_64   = 201.00931639928152;       // lgamma(64)
    const double LN_HALF = -0.6931471805599453;
    const double LN_TENTH = -2.302585092994046;

    double acc = 0.0;
    for (int i = t; i < KK * DD; i += TPB) {
        int d = i & (DD - 1);
        float lam = lambda_mu[d];
        float var = lam * lam * shR[d];
        float diff = mu[i] - bv[i];
        float bb = bv[i];
        acc += (double)(0.5f * diff * diff / var) + (double)(0.5f * bb * bb);
    }
    for (int d = t; d < DD; d += TPB) {
        float lam = lambda_mu[d];
        float var = lam * lam * shR[d];
        acc += 0.5 * (double)KK * (double)__logf(var);
        acc -= 0.5 * LN_HALF - LG_HALF - 0.5 * (double)lam - 0.5 * (double)__expf(lam);
    }
    for (int k = t; k < KK; k += TPB) {
        float rk = rv[k], Ck = Cv[k];
        acc -= cc * (double)__logf(Ck) - (cc - 1.0) * (double)rk
               - (double)Ck * (double)__expf(-rk) - LG_C;
        acc -= gg * lgG - (gg - 1.0) * (double)Ck
               - Gd * (double)__expf(-Ck) - LG_G;
    }
    const float4* p4 = reinterpret_cast<const float4*>(g_partial);
    for (int i = t; i < ZGRID / 4; i += TPB) {
        float4 v = p4[i];
        acc -= (double)v.x + (double)v.y + (double)v.z + (double)v.w;
    }

    double* dred = reinterpret_cast<double*>(SZ);    // overlay (SZ no longer needed)
    dred[t] = acc;
    __syncthreads();
#pragma unroll
    for (int s = 64; s; s >>= 1) {
        if (t < s) dred[t] += dred[t + s];
        __syncthreads();
    }
    if (t == 0) {
        double total = dred[0];
        double sumlp = (double)g_sumlogpi;
        double G0 = LG_64 + 63.0 * LN_TENTH + sumlp;          // per-row constant in con
        total -= (double)NN * G0;                             // z-loss constant part
        total += (63.0 / 64.0) * sumlp;                       // pi_loss
        total += (double)KK * 0.5 * (double)DD * DLOG2PI;     // mu_loss const
        total += 0.5 * (double)KK * (double)DD * DLOG2PI;     // b_loss const
        out[0] = (float)total;
        atomicExch(&g_ctr, 0u);                               // reset for graph replay
    }
}

// ---------------- launch ----------------
extern "C" void kernel_launch(void* const* d_in, const int* in_sizes, int n_in,
                              void* d_out, int out_size) {
    const float* met = (const float*)d_in[0];
    const float* mu  = (const float*)d_in[1];
    const float* pi  = (const float*)d_in[2];
    const float* lam = (const float*)d_in[3];
    const float* b   = (const float*)d_in[4];
    const float* C   = (const float*)d_in[5];
    const float* r   = (const float*)d_in[6];
    const float* z   = (const float*)d_in[7];
    (void)in_sizes; (void)n_in; (void)out_size;

    zloss_kernel<<<ZGRID, TPB>>>(met, z, mu, pi, r, lam, b, C, (float*)d_out);
}